// round 2
// baseline (speedup 1.0000x reference)
#include <cuda_runtime.h>
#include <math.h>

#define N_NODES 8192
#define N_EDGES 65536
#define CDIM 64
#define NB 8
#define NELEM 10
#define NGRAPH 8

// Scratch (device globals; no allocation allowed)
__device__ float g_s[N_NODES * CDIM];      // current h[:,0,:]
__device__ float g_m[N_NODES * CDIM];      // message accumulator
__device__ float g_energy[N_NODES];        // per-node energy
__device__ float g_ef[N_EDGES * NB];       // edge radial features
__device__ int   g_elem[N_NODES];          // element index per node

// ---------------------------------------------------------------------------
// init: element lookup, s = W_embed[elem], energy = atomic_energies[elem],
// zero m, zero d_out
// ---------------------------------------------------------------------------
__global__ void init_kernel(const float* __restrict__ node_attrs,
                            const float* __restrict__ atomic_energies,
                            const float* __restrict__ W_embed,
                            float* __restrict__ d_out) {
    int n = blockIdx.x * blockDim.x + threadIdx.x;
    if (n >= N_NODES) return;
    if (n < NGRAPH) d_out[n] = 0.0f;

    const float* row = node_attrs + n * NELEM;
    int el = 0;
#pragma unroll
    for (int k = 0; k < NELEM; k++)
        if (row[k] > 0.5f) el = k;
    g_elem[n] = el;
    g_energy[n] = atomic_energies[el];

    const float4* we = (const float4*)(W_embed + el * CDIM);
    float4* srow = (float4*)(g_s + n * CDIM);
    float4* mrow = (float4*)(g_m + n * CDIM);
#pragma unroll
    for (int q = 0; q < CDIM / 4; q++) {
        srow[q] = we[q];
        mrow[q] = make_float4(0.f, 0.f, 0.f, 0.f);
    }
}

// ---------------------------------------------------------------------------
// edge radial features: bessel * polynomial cutoff (sh[:,0]=1, u unused)
// ---------------------------------------------------------------------------
__global__ void edge_feat_kernel(const float* __restrict__ positions,
                                 const int* __restrict__ edge_index) {
    int e = blockIdx.x * blockDim.x + threadIdx.x;
    if (e >= N_EDGES) return;
    int snd = edge_index[e];
    int rcv = edge_index[N_EDGES + e];

    float dx = positions[rcv * 3 + 0] - positions[snd * 3 + 0];
    float dy = positions[rcv * 3 + 1] - positions[snd * 3 + 1];
    float dz = positions[rcv * 3 + 2] - positions[snd * 3 + 2];
    float r = sqrtf(dx * dx + dy * dy + dz * dz);
    float rs = fmaxf(r, 1e-9f);
    float t = r * 0.2f;  // r / R_MAX

    float4 o0, o1;
    if (t < 1.0f) {
        // env = 1 - 21 t^5 + 35 t^6 - 15 t^7
        float t2 = t * t;
        float t5 = t2 * t2 * t;
        float env = 1.0f - 21.0f * t5 + 35.0f * t5 * t - 15.0f * t5 * t2;
        float pref = 0.6324555320336759f; // sqrt(2/5)
        float scale = pref * env / rs;
        float x = 0.62831853071795864769f * rs; // pi * r_safe / 5
        float s1, c1;
        __sincosf(x, &s1, &c1);
        // Chebyshev recurrence: sin((n+1)x) = 2 cos(x) sin(nx) - sin((n-1)x)
        float twoc = 2.0f * c1;
        float sm1 = 0.0f, sn = s1;
        float b[NB];
#pragma unroll
        for (int k = 0; k < NB; k++) {
            b[k] = sn * scale;
            float nxt = twoc * sn - sm1;
            sm1 = sn; sn = nxt;
        }
        o0 = make_float4(b[0], b[1], b[2], b[3]);
        o1 = make_float4(b[4], b[5], b[6], b[7]);
    } else {
        o0 = make_float4(0.f, 0.f, 0.f, 0.f);
        o1 = o0;
    }
    float4* out = (float4*)(g_ef + e * NB);
    out[0] = o0;
    out[1] = o1;
}

__device__ __forceinline__ float silu(float x) {
    return __fdividef(x, 1.0f + __expf(-x));
}

// ---------------------------------------------------------------------------
// edge MLP: ef(8) ->64 ->64 ->64 (l=0 slice of w3), msg = R0*s[snd],
// atomicAdd into m[rcv]. One thread per edge; weights in smem.
// ---------------------------------------------------------------------------
__global__ __launch_bounds__(128) void edge_mlp_kernel(
    const float* __restrict__ w1, const float* __restrict__ b1,
    const float* __restrict__ w2, const float* __restrict__ b2,
    const float* __restrict__ w3, const int* __restrict__ edge_index) {
    __shared__ float sw1[NB * CDIM];
    __shared__ float sb1[CDIM];
    __shared__ float sw2[CDIM * CDIM];
    __shared__ float sb2[CDIM];
    __shared__ float sw3[CDIM * CDIM];

    int tid = threadIdx.x;
    for (int k = tid; k < NB * CDIM; k += 128) sw1[k] = w1[k];
    if (tid < CDIM) { sb1[tid] = b1[tid]; sb2[tid] = b2[tid]; }
    for (int k = tid; k < CDIM * CDIM; k += 128) sw2[k] = w2[k];
    for (int k = tid; k < CDIM * CDIM; k += 128) {
        int c = k >> 6, j = k & 63;
        sw3[k] = w3[c * 256 + j];   // l=0 slice: columns 0..63 of (64,256)
    }
    __syncthreads();

    int e = blockIdx.x * 128 + tid;
    if (e >= N_EDGES) return;

    const float4* efv = (const float4*)(g_ef + e * NB);
    float4 e0 = efv[0], e1 = efv[1];
    float ef[NB] = {e0.x, e0.y, e0.z, e0.w, e1.x, e1.y, e1.z, e1.w};

    float a[CDIM], b[CDIM];
    // layer 1: 8 -> 64
#pragma unroll
    for (int j = 0; j < CDIM; j++) a[j] = sb1[j];
#pragma unroll
    for (int c = 0; c < NB; c++) {
        float x = ef[c];
        const float4* wr = (const float4*)(sw1 + c * CDIM);
#pragma unroll
        for (int j4 = 0; j4 < CDIM / 4; j4++) {
            float4 w = wr[j4];
            a[4 * j4 + 0] += x * w.x;
            a[4 * j4 + 1] += x * w.y;
            a[4 * j4 + 2] += x * w.z;
            a[4 * j4 + 3] += x * w.w;
        }
    }
#pragma unroll
    for (int j = 0; j < CDIM; j++) a[j] = silu(a[j]);

    // layer 2: 64 -> 64
#pragma unroll
    for (int j = 0; j < CDIM; j++) b[j] = sb2[j];
#pragma unroll
    for (int c = 0; c < CDIM; c++) {
        float x = a[c];
        const float4* wr = (const float4*)(sw2 + c * CDIM);
#pragma unroll
        for (int j4 = 0; j4 < CDIM / 4; j4++) {
            float4 w = wr[j4];
            b[4 * j4 + 0] += x * w.x;
            b[4 * j4 + 1] += x * w.y;
            b[4 * j4 + 2] += x * w.z;
            b[4 * j4 + 3] += x * w.w;
        }
    }
#pragma unroll
    for (int j = 0; j < CDIM; j++) b[j] = silu(b[j]);

    // layer 3: 64 -> 64 (no bias, no act) into a
#pragma unroll
    for (int j = 0; j < CDIM; j++) a[j] = 0.0f;
#pragma unroll
    for (int c = 0; c < CDIM; c++) {
        float x = b[c];
        const float4* wr = (const float4*)(sw3 + c * CDIM);
#pragma unroll
        for (int j4 = 0; j4 < CDIM / 4; j4++) {
            float4 w = wr[j4];
            a[4 * j4 + 0] += x * w.x;
            a[4 * j4 + 1] += x * w.y;
            a[4 * j4 + 2] += x * w.z;
            a[4 * j4 + 3] += x * w.w;
        }
    }

    // message: msg = R0 * s[snd]; scatter into m[rcv]
    int snd = edge_index[e];
    int rcv = edge_index[N_EDGES + e];
    const float4* srow = (const float4*)(g_s + snd * CDIM);
    float* mrow = g_m + rcv * CDIM;
#pragma unroll
    for (int j4 = 0; j4 < CDIM / 4; j4++) {
        float4 sv = srow[j4];
        atomicAdd(mrow + 4 * j4 + 0, a[4 * j4 + 0] * sv.x);
        atomicAdd(mrow + 4 * j4 + 1, a[4 * j4 + 1] * sv.y);
        atomicAdd(mrow + 4 * j4 + 2, a[4 * j4 + 2] * sv.z);
        atomicAdd(mrow + 4 * j4 + 3, a[4 * j4 + 3] * sv.w);
    }
}

// ---------------------------------------------------------------------------
// node update: f = (m/8) @ W_lin0; h = f*(w0+w1*f+w2*f^2) + sc*s;
// energy += h . W_read; s = h; m = 0 (ready for next interaction / replay)
// ---------------------------------------------------------------------------
__global__ __launch_bounds__(128) void node_kernel(
    const float* __restrict__ Wlin0,  // (64,64), l=0 block
    const float* __restrict__ Wprod,  // (3,10,64)
    const float* __restrict__ Wsc,    // (10,64)
    const float* __restrict__ Wread)  // (64,)
{
    __shared__ float swl[CDIM * CDIM];
    __shared__ float swr[CDIM];
    int tid = threadIdx.x;
    for (int k = tid; k < CDIM * CDIM; k += 128) swl[k] = Wlin0[k];
    if (tid < CDIM) swr[tid] = Wread[tid];
    __syncthreads();

    int n = blockIdx.x * 128 + tid;
    if (n >= N_NODES) return;

    float m[CDIM];
    {
        float4* mrow = (float4*)(g_m + n * CDIM);
#pragma unroll
        for (int q = 0; q < CDIM / 4; q++) {
            float4 v = mrow[q];
            m[4 * q + 0] = v.x * 0.125f;
            m[4 * q + 1] = v.y * 0.125f;
            m[4 * q + 2] = v.z * 0.125f;
            m[4 * q + 3] = v.w * 0.125f;
            mrow[q] = make_float4(0.f, 0.f, 0.f, 0.f);
        }
    }

    float f[CDIM];
#pragma unroll
    for (int j = 0; j < CDIM; j++) f[j] = 0.0f;
#pragma unroll
    for (int c = 0; c < CDIM; c++) {
        float x = m[c];
        const float4* wr = (const float4*)(swl + c * CDIM);
#pragma unroll
        for (int j4 = 0; j4 < CDIM / 4; j4++) {
            float4 w = wr[j4];
            f[4 * j4 + 0] += x * w.x;
            f[4 * j4 + 1] += x * w.y;
            f[4 * j4 + 2] += x * w.z;
            f[4 * j4 + 3] += x * w.w;
        }
    }

    int el = g_elem[n];
    const float* w0 = Wprod + (0 * NELEM + el) * CDIM;
    const float* w1p = Wprod + (1 * NELEM + el) * CDIM;
    const float* w2p = Wprod + (2 * NELEM + el) * CDIM;
    const float* sc = Wsc + el * CDIM;
    float* srow = g_s + n * CDIM;

    float energy = 0.0f;
#pragma unroll
    for (int c = 0; c < CDIM; c++) {
        float fc = f[c];
        float sp = srow[c];
        float h = fc * (w0[c] + w1p[c] * fc + w2p[c] * fc * fc) + sc[c] * sp;
        srow[c] = h;
        energy += h * swr[c];
    }
    g_energy[n] += energy;
}

// ---------------------------------------------------------------------------
// final: segment-sum node energies by graph
// ---------------------------------------------------------------------------
__global__ void final_kernel(const int* __restrict__ batch,
                             float* __restrict__ d_out) {
    __shared__ float bins[NGRAPH];
    if (threadIdx.x < NGRAPH) bins[threadIdx.x] = 0.0f;
    __syncthreads();
    int n = blockIdx.x * blockDim.x + threadIdx.x;
    if (n < N_NODES) atomicAdd(&bins[batch[n]], g_energy[n]);
    __syncthreads();
    if (threadIdx.x < NGRAPH) atomicAdd(d_out + threadIdx.x, bins[threadIdx.x]);
}

// ---------------------------------------------------------------------------
extern "C" void kernel_launch(void* const* d_in, const int* in_sizes, int n_in,
                              void* d_out, int out_size) {
    const float* positions       = (const float*)d_in[0];
    const float* node_attrs      = (const float*)d_in[1];
    const int*   edge_index      = (const int*)d_in[2];
    const int*   batch           = (const int*)d_in[3];
    const float* atomic_energies = (const float*)d_in[4];
    const float* W_embed         = (const float*)d_in[5];
    const float* rw1             = (const float*)d_in[6];
    const float* rb1             = (const float*)d_in[7];
    const float* rw2             = (const float*)d_in[8];
    const float* rb2             = (const float*)d_in[9];
    const float* rw3             = (const float*)d_in[10];
    const float* Wlin            = (const float*)d_in[11];
    const float* Wprod           = (const float*)d_in[12];
    const float* Wsc             = (const float*)d_in[13];
    const float* Wread           = (const float*)d_in[14];
    float* out = (float*)d_out;

    init_kernel<<<N_NODES / 128, 128>>>(node_attrs, atomic_energies, W_embed, out);
    edge_feat_kernel<<<N_EDGES / 128, 128>>>(positions, edge_index);
    for (int i = 0; i < 2; i++) {
        edge_mlp_kernel<<<N_EDGES / 128, 128>>>(
            rw1 + i * NB * CDIM, rb1 + i * CDIM,
            rw2 + i * CDIM * CDIM, rb2 + i * CDIM,
            rw3 + i * CDIM * 256, edge_index);
        node_kernel<<<N_NODES / 128, 128>>>(
            Wlin + i * 4 * CDIM * CDIM,
            Wprod + i * 3 * NELEM * CDIM,
            Wsc + i * NELEM * CDIM,
            Wread + i * CDIM);
    }
    final_kernel<<<N_NODES / 256, 256>>>(batch, out);
}